// round 14
// baseline (speedup 1.0000x reference)
#include <cuda_runtime.h>
#include <cuda_bf16.h>
#include <mma.h>
#include <math.h>
#include <cstdint>

using namespace nvcuda;
typedef __nv_bfloat16 bf16;

// ---------------- problem constants ----------------
#define QL 512
#define ML 512
#define KL 1024          // QL + ML
#define BSZ 4
#define NH 16
#define DH 64
#define DM 1024
#define DI 4096
#define NV 32000
#define NL 6
#define HD3 3072         // 3*NH*DH

// ---------------- fp32 scratch ----------------
__device__ float g_h[(size_t)QL * BSZ * DM];
__device__ float g_S[(size_t)BSZ * NH * QL * KL];     // AC
__device__ float g_D[(size_t)BSZ * NH * QL * KL];     // BD (unshifted)
__device__ float g_ao[(size_t)QL * BSZ * DM];
__device__ float g_ff[(size_t)QL * BSZ * DM];
__device__ float g_logits[(size_t)QL * BSZ * NV];

// ---------------- bf16 weight arena ----------------
__device__ bf16 wb_qkv[(size_t)NL * HD3 * DM];
__device__ bf16 wb_r[(size_t)NL * DM * DM];
__device__ bf16 wb_o[(size_t)NL * DM * DM];
__device__ bf16 wb_f1[(size_t)NL * DI * DM];
__device__ bf16 wb_f2[(size_t)NL * DI * DM];
__device__ bf16 wb_emb[(size_t)NV * DM];

// ---------------- bf16 activation buffers ----------------
__device__ bf16 b_cat[(size_t)KL * BSZ * DM];
__device__ bf16 b_heads[(size_t)KL * BSZ * HD3];
__device__ bf16 b_pos[(size_t)KL * DM];
__device__ bf16 b_r[(size_t)KL * DM];
__device__ bf16 b_qc[(size_t)BSZ * NH * QL * DH];
__device__ bf16 b_qr[(size_t)BSZ * NH * QL * DH];
__device__ bf16 b_P[(size_t)BSZ * NH * QL * KL];
__device__ bf16 b_av[(size_t)QL * BSZ * DM];
__device__ bf16 b_h[(size_t)QL * BSZ * DM];
__device__ bf16 b_ffh[(size_t)QL * BSZ * DI];

// ---------------- cp.async helpers ----------------
__device__ __forceinline__ void cpa16(void* dst, const void* src, bool pred) {
    unsigned d = (unsigned)__cvta_generic_to_shared(dst);
    int sz = pred ? 16 : 0;
    asm volatile("cp.async.cg.shared.global [%0], [%1], 16, %2;\n"
                 :: "r"(d), "l"(src), "r"(sz));
}
__device__ __forceinline__ void cpa_commit() {
    asm volatile("cp.async.commit_group;\n" ::: "memory");
}

// ---------------- fp32 -> bf16 bulk convert ----------------
__global__ void f2b_kernel(const float* __restrict__ in, bf16* __restrict__ out, size_t n8) {
    size_t i = (size_t)blockIdx.x * 256 + threadIdx.x;
    if (i >= n8) return;
    const float4* in4 = (const float4*)in;
    float4 a = in4[2 * i], b = in4[2 * i + 1];
    __nv_bfloat162 h0 = __floats2bfloat162_rn(a.x, a.y);
    __nv_bfloat162 h1 = __floats2bfloat162_rn(a.z, a.w);
    __nv_bfloat162 h2 = __floats2bfloat162_rn(b.x, b.y);
    __nv_bfloat162 h3 = __floats2bfloat162_rn(b.z, b.w);
    uint4 u;
    u.x = *(unsigned*)&h0; u.y = *(unsigned*)&h1;
    u.z = *(unsigned*)&h2; u.w = *(unsigned*)&h3;
    ((uint4*)out)[i] = u;
}

// ---------------- positional embedding (bf16) ----------------
__global__ void posemb_kernel(bf16* __restrict__ pos) {
    int p = blockIdx.x;
    int j = threadIdx.x;
    float posv = (float)(KL - 1 - p);
    float inv = expf(-(float)(2 * j) * (9.210340371976184f / 1024.0f));
    float a = posv * inv;
    pos[(size_t)p * DM + j]       = __float2bfloat16(sinf(a));
    pos[(size_t)p * DM + 512 + j] = __float2bfloat16(cosf(a));
}

// ---------------- embedding lookup (fp32 residual) ----------------
__global__ void embed_kernel(const int* __restrict__ data,
                             const float* __restrict__ emb,
                             float* __restrict__ h) {
    int row = blockIdx.x;
    int tok = data[row];
    const float4* src = (const float4*)(emb + (size_t)tok * DM);
    float4* dst = (float4*)(h + (size_t)row * DM);
    int d = threadIdx.x;
    float4 f = src[d];
    f.x *= 32.0f; f.y *= 32.0f; f.z *= 32.0f; f.w *= 32.0f;
    dst[d] = f;
}

// ---------------- concat [mems_l ; h] -> bf16 cat ----------------
__global__ void concat_kernel(const float* __restrict__ mems_l,
                              const float* __restrict__ h,
                              bf16* __restrict__ cat) {
    int row = blockIdx.x;
    const float4* src = (row < ML * BSZ)
        ? (const float4*)(mems_l + (size_t)row * DM)
        : (const float4*)(h + (size_t)(row - ML * BSZ) * DM);
    float4 f = src[threadIdx.x];
    __nv_bfloat162 h0 = __floats2bfloat162_rn(f.x, f.y);
    __nv_bfloat162 h1 = __floats2bfloat162_rn(f.z, f.w);
    uint2 u; u.x = *(unsigned*)&h0; u.y = *(unsigned*)&h1;
    ((uint2*)(cat + (size_t)row * DM))[threadIdx.x] = u;
}

// ---------------- BIG-TILE bf16 wmma GEMM (NT): C[m,n] = sum_k A[m,k]*B[n,k] ----------------
// Block 128x256x32, 256 thr, 8 warps (2x4), warp tile 64x64 (4x4 m16n16k16).
// M mult 128, N mult 256, K mult 32. OUT: 0 fp32, 1 bf16, 2 bf16 +bias,relu.
// Dynamic smem: 2 stages x (A 128x40 + B 256x40) bf16 = 61440 B.
#define BG_SMEM 61440

template <int OUT>
__global__ void __launch_bounds__(256, 1)
wgemmB(const bf16* __restrict__ A, int lda,
       const bf16* __restrict__ B, int ldb,
       void* __restrict__ Cv, int ldc,
       const float* __restrict__ bias, int K) {
    extern __shared__ __align__(16) char dsm[];
    bf16* As = (bf16*)dsm;                   // [2][128*40]
    bf16* Bs = (bf16*)dsm + 2 * 128 * 40;    // [2][256*40]
    int tid = threadIdx.x;
    int warp = tid >> 5, wr = warp >> 2, wc = warp & 3;
    int lane = tid & 31;
    int m0 = blockIdx.x * 128, n0 = blockIdx.y * 256;

    wmma::fragment<wmma::accumulator, 16, 16, 16, float> acc[4][4];
#pragma unroll
    for (int i = 0; i < 4; i++)
#pragma unroll
        for (int j = 0; j < 4; j++) wmma::fill_fragment(acc[i][j], 0.0f);

    // loaders: A = 512 16B-chunks (2/thread), B = 1024 chunks (4/thread)
    int ar0 = tid >> 2, ac8 = (tid & 3) * 8;       // A chunk 0: row ar0
    int ar1 = ar0 + 64;                            // A chunk 1
    auto load_stage = [&](int st, int k0) {
        bf16* a_s = As + st * 128 * 40;
        bf16* b_s = Bs + st * 256 * 40;
        cpa16(a_s + ar0 * 40 + ac8, A + (size_t)(m0 + ar0) * lda + k0 + ac8, true);
        cpa16(a_s + ar1 * 40 + ac8, A + (size_t)(m0 + ar1) * lda + k0 + ac8, true);
#pragma unroll
        for (int q = 0; q < 4; q++) {
            int br = ar0 + q * 64;                 // rows 0..255
            cpa16(b_s + br * 40 + ac8, B + (size_t)(n0 + br) * ldb + k0 + ac8, true);
        }
        cpa_commit();
    };

    int nk = K >> 5;
    load_stage(0, 0);
    for (int i = 0; i < nk; i++) {
        int st = i & 1;
        if (i + 1 < nk) {
            load_stage(st ^ 1, (i + 1) << 5);
            asm volatile("cp.async.wait_group 1;\n" ::: "memory");
        } else {
            asm volatile("cp.async.wait_group 0;\n" ::: "memory");
        }
        __syncthreads();

        bf16* a_s = As + st * 128 * 40;
        bf16* b_s = Bs + st * 256 * 40;
#pragma unroll
        for (int ks = 0; ks < 2; ks++) {
            wmma::fragment<wmma::matrix_a, 16, 16, 16, bf16, wmma::row_major> af[4];
#pragma unroll
            for (int mi = 0; mi < 4; mi++)
                wmma::load_matrix_sync(af[mi], a_s + (wr * 64 + mi * 16) * 40 + ks * 16, 40);
#pragma unroll
            for (int ni = 0; ni < 4; ni++) {
                wmma::fragment<wmma::matrix_b, 16, 16, 16, bf16, wmma::col_major> bfr;
                wmma::load_matrix_sync(bfr, b_s + (wc * 64 + ni * 16) * 40 + ks * 16, 40);
#pragma unroll
                for (int mi = 0; mi < 4; mi++)
                    wmma::mma_sync(acc[mi][ni], af[mi], bfr, acc[mi][ni]);
            }
        }
        __syncthreads();
    }

    if (OUT == 0) {
        float* Cb = (float*)Cv;
#pragma unroll
        for (int mi = 0; mi < 4; mi++)
#pragma unroll
            for (int ni = 0; ni < 4; ni++)
                wmma::store_matrix_sync(
                    Cb + (size_t)(m0 + wr * 64 + mi * 16) * ldc + n0 + wc * 64 + ni * 16,
                    acc[mi][ni], ldc, wmma::mem_row_major);
    } else {
        bf16* Cb = (bf16*)Cv;
        float* wbuf = (float*)dsm + warp * 320;   // 16x20 staging, ldm=20 floats=80B (16B mult)
        int r = lane >> 1, ch = (lane & 1) * 8;
#pragma unroll
        for (int mi = 0; mi < 4; mi++)
#pragma unroll
            for (int ni = 0; ni < 4; ni++) {
                wmma::store_matrix_sync(wbuf, acc[mi][ni], 20, wmma::mem_row_major);
                __syncwarp();
                int gn = n0 + wc * 64 + ni * 16 + ch;
                int gm = m0 + wr * 64 + mi * 16 + r;
                float v[8];
#pragma unroll
                for (int t = 0; t < 8; t++) v[t] = wbuf[r * 20 + ch + t];
                if (OUT == 2) {
#pragma unroll
                    for (int t = 0; t < 8; t++) v[t] = fmaxf(v[t] + bias[gn + t], 0.0f);
                }
                __nv_bfloat162 h0 = __floats2bfloat162_rn(v[0], v[1]);
                __nv_bfloat162 h1 = __floats2bfloat162_rn(v[2], v[3]);
                __nv_bfloat162 h2 = __floats2bfloat162_rn(v[4], v[5]);
                __nv_bfloat162 h3 = __floats2bfloat162_rn(v[6], v[7]);
                uint4 u;
                u.x = *(unsigned*)&h0; u.y = *(unsigned*)&h1;
                u.z = *(unsigned*)&h2; u.w = *(unsigned*)&h3;
                *(uint4*)(Cb + (size_t)gm * ldc + gn) = u;
                __syncwarp();
            }
    }
}

// ---------------- bf16 wmma GEMM, 128x128 (attention shapes, batched) ----------------
template <int BROW, int OUT>
__global__ void __launch_bounds__(256, 2)
wgemmb(const bf16* __restrict__ A, int lda, size_t sA1, size_t sA2,
       const bf16* __restrict__ B, int ldb, size_t sB1, size_t sB2,
       void* __restrict__ Cv, int ldc, size_t sC1, size_t sC2,
       const float* __restrict__ bias, int N, int K) {
    int zn = blockIdx.z >> 2, zb = blockIdx.z & 3;
    const bf16* Ab = A + (size_t)zn * sA1 + (size_t)zb * sA2;
    const bf16* Bb = B + (size_t)zn * sB1 + (size_t)zb * sB2;
    int m0 = blockIdx.x * 128, n0 = blockIdx.y * 128;
    int tid = threadIdx.x;
    int warp = tid >> 5, wr = warp >> 2, wc = warp & 3;
    int lane = tid & 31;

    __shared__ __align__(16) bf16 As[2][128 * 40];
    __shared__ __align__(16) bf16 Bs[2][128 * 40];

    wmma::fragment<wmma::accumulator, 16, 16, 16, float> acc[4][2];
#pragma unroll
    for (int i = 0; i < 4; i++)
#pragma unroll
        for (int j = 0; j < 2; j++) wmma::fill_fragment(acc[i][j], 0.0f);

    int arow0 = tid >> 2, ac0 = (tid & 3) * 8, arow1 = arow0 + 64;
    int kr0 = 0, kr1 = 0, nc0 = 0;
    bool g0 = true, g1 = true, gn = true;
    if (BROW == 0) {
        g0 = (n0 + arow0) < N;
        g1 = (n0 + arow1) < N;
    } else {
        kr0 = tid >> 4; kr1 = kr0 + 16;
        nc0 = (tid & 15) * 8;
        gn = (n0 + nc0) < N;
    }

    auto load_stage = [&](int st, int k0) {
        cpa16(&As[st][arow0 * 40 + ac0], Ab + (size_t)(m0 + arow0) * lda + k0 + ac0, true);
        cpa16(&As[st][arow1 * 40 + ac0], Ab + (size_t)(m0 + arow1) * lda + k0 + ac0, true);
        if (BROW == 0) {
            cpa16(&Bs[st][arow0 * 40 + ac0], Bb + (size_t)(n0 + arow0) * ldb + k0 + ac0, g0);
            cpa16(&Bs[st][arow1 * 40 + ac0], Bb + (size_t)(n0 + arow1) * ldb + k0 + ac0, g1);
        } else {
            cpa16(&Bs[st][kr0 * 136 + nc0], Bb + (size_t)(k0 + kr0) * ldb + n0 + nc0, gn);
            cpa16(&Bs[st][kr1 * 136 + nc0], Bb + (size_t)(k0 + kr1) * ldb + n0 + nc0, gn);
        }
        cpa_commit();
    };

    int nk = K >> 5;
    load_stage(0, 0);
    for (int i = 0; i < nk; i++) {
        int st = i & 1;
        if (i + 1 < nk) {
            load_stage(st ^ 1, (i + 1) << 5);
            asm volatile("cp.async.wait_group 1;\n" ::: "memory");
        } else {
            asm volatile("cp.async.wait_group 0;\n" ::: "memory");
        }
        __syncthreads();

#pragma unroll
        for (int ks = 0; ks < 2; ks++) {
            wmma::fragment<wmma::matrix_a, 16, 16, 16, bf16, wmma::row_major> af[4];
#pragma unroll
            for (int mi = 0; mi < 4; mi++)
                wmma::load_matrix_sync(af[mi], &As[st][(wr * 64 + mi * 16) * 40 + ks * 16], 40);
            if (BROW == 0) {
                wmma::fragment<wmma::matrix_b, 16, 16, 16, bf16, wmma::col_major> bfr[2];
#pragma unroll
                for (int ni = 0; ni < 2; ni++)
                    wmma::load_matrix_sync(bfr[ni], &Bs[st][(wc * 32 + ni * 16) * 40 + ks * 16], 40);
#pragma unroll
                for (int mi = 0; mi < 4; mi++)
#pragma unroll
                    for (int ni = 0; ni < 2; ni++)
                        wmma::mma_sync(acc[mi][ni], af[mi], bfr[ni], acc[mi][ni]);
            } else {
                wmma::fragment<wmma::matrix_b, 16, 16, 16, bf16, wmma::row_major> bfr[2];
#pragma unroll
                for (int ni = 0; ni < 2; ni++)
                    wmma::load_matrix_sync(bfr[ni], &Bs[st][ks * 16 * 136 + wc * 32 + ni * 16], 136);
#pragma unroll
                for (int mi = 0; mi < 4; mi++)
#pragma unroll
                    for (int ni = 0; ni < 2; ni++)
                        wmma::mma_sync(acc[mi][ni], af[mi], bfr[ni], acc[mi][ni]);
            }
        }
        __syncthreads();
    }

    if (OUT == 0) {
        float* Cb = (float*)Cv + (size_t)zn * sC1 + (size_t)zb * sC2;
#pragma unroll
        for (int mi = 0; mi < 4; mi++)
#pragma unroll
            for (int ni = 0; ni < 2; ni++) {
                int cn = n0 + wc * 32 + ni * 16;
                if (cn < N)
                    wmma::store_matrix_sync(Cb + (size_t)(m0 + wr * 64 + mi * 16) * ldc + cn,
                                            acc[mi][ni], ldc, wmma::mem_row_major);
            }
    } else {
        bf16* Cb = (bf16*)Cv + (size_t)zn * sC1 + (size_t)zb * sC2;
        float* wbuf = ((float*)As) + warp * 320;
        int r = lane >> 1, ch = (lane & 1) * 8;
#pragma unroll
        for (int mi = 0; mi < 4; mi++)
#pragma unroll
            for (int ni = 0; ni < 2; ni++) {
                wmma::store_matrix_sync(wbuf, acc[mi][ni], 20, wmma::mem_row_major);
                __syncwarp();
                int gn = n0 + wc * 32 + ni * 16 + ch;
                if (gn < N) {
                    int gm = m0 + wr * 64 + mi * 16 + r;
                    float v[8];
#pragma unroll
                    for (int t = 0; t < 8; t++) v[t] = wbuf[r * 20 + ch + t];
                    if (OUT == 2) {
#pragma unroll
                        for (int t = 0; t < 8; t++) v[t] = fmaxf(v[t] + bias[gn + t], 0.0f);
                    }
                    __nv_bfloat162 h0 = __floats2bfloat162_rn(v[0], v[1]);
                    __nv_bfloat162 h1 = __floats2bfloat162_rn(v[2], v[3]);
                    __nv_bfloat162 h2 = __floats2bfloat162_rn(v[4], v[5]);
                    __nv_bfloat162 h3 = __floats2bfloat162_rn(v[6], v[7]);
                    uint4 u;
                    u.x = *(unsigned*)&h0; u.y = *(unsigned*)&h1;
                    u.z = *(unsigned*)&h2; u.w = *(unsigned*)&h3;
                    *(uint4*)(Cb + (size_t)gm * ldc + gn) = u;
                }
                __syncwarp();
            }
    }
}

// ---------------- qc = q + r_w_bias, qr = q + r_r_bias (bf16 in/out) ----------------
__global__ void qcqr_kernel(const bf16* __restrict__ heads,
                            const float* __restrict__ rwb, const float* __restrict__ rrb,
                            bf16* __restrict__ qc, bf16* __restrict__ qr) {
    int i = blockIdx.x, b = blockIdx.y;
    int tid = threadIdx.x;
#pragma unroll
    for (int k = 0; k < 4; k++) {
        int dg = tid + k * 256;
        int n = dg >> 6, d = dg & 63;
        float q = __bfloat162float(heads[((size_t)(ML + i) * BSZ + b) * HD3 + n * DH + d]);
        size_t o = ((size_t)(n * 4 + b) * QL + i) * DH + d;
        qc[o] = __float2bfloat16(q + rwb[dg]);
        qr[o] = __float2bfloat16(q + rrb[dg]);
    }
}

// ---------------- fused rel-shift + mask + softmax -> bf16 P ----------------
__global__ void __launch_bounds__(256)
softmax_kernel(const float* __restrict__ S, const float* __restrict__ D,
               bf16* __restrict__ P) {
    int i = blockIdx.x;
    int z = blockIdx.y;
    const float* row = S + ((size_t)z * QL + i) * KL;
    const float* drow = D + ((size_t)z * QL + i) * KL + (QL - 1 - i);
    bf16* prow = P + ((size_t)z * QL + i) * KL;
    int jmax = i + ML;
    __shared__ float sc[KL];
    __shared__ float red[256];
    int tid = threadIdx.x;

    float mx = -1e30f;
    for (int j = tid; j <= jmax; j += 256) {
        float s = (row[j] + drow[j]) * 0.125f;
        sc[j] = s;
        mx = fmaxf(mx, s);
    }
    red[tid] = mx;
    __syncthreads();
    for (int t = 128; t > 0; t >>= 1) {
        if (tid < t) red[tid] = fmaxf(red[tid], red[tid + t]);
        __syncthreads();
    }
    float m = red[0];
    __syncthreads();

    float sum = 0.0f;
    for (int j = tid; j <= jmax; j += 256) {
        float e = expf(sc[j] - m);
        sc[j] = e;
        sum += e;
    }
    red[tid] = sum;
    __syncthreads();
    for (int t = 128; t > 0; t >>= 1) {
        if (tid < t) red[tid] += red[tid + t];
        __syncthreads();
    }
    float inv = 1.0f / red[0];
    __syncthreads();

    for (int j = tid; j <= jmax; j += 256) prow[j] = __float2bfloat16(sc[j] * inv);
    bf16 zero = __float2bfloat16(0.0f);
    for (int j = jmax + 1 + tid; j < KL; j += 256) prow[j] = zero;
}

// ---------------- fused residual (+bias) + layernorm; fp32 + bf16 outputs ----------------
__global__ void __launch_bounds__(256)
ln_kernel(const float* __restrict__ x, const float* __restrict__ y,
          const float* __restrict__ extra,
          const float* __restrict__ g, const float* __restrict__ b,
          float* __restrict__ out, bf16* __restrict__ outb) {
    int row = blockIdx.x;
    __shared__ float buf[DM];
    __shared__ float red[256];
    int tid = threadIdx.x;
    float s = 0.0f;
    for (int d = tid; d < DM; d += 256) {
        float v = x[(size_t)row * DM + d] + y[(size_t)row * DM + d];
        if (extra) v += extra[d];
        buf[d] = v;
        s += v;
    }
    red[tid] = s;
    __syncthreads();
    for (int t = 128; t > 0; t >>= 1) {
        if (tid < t) red[tid] += red[tid + t];
        __syncthreads();
    }
    float mu = red[0] * (1.0f / DM);
    __syncthreads();
    float s2 = 0.0f;
    for (int d = tid; d < DM; d += 256) {
        float v = buf[d] - mu;
        s2 += v * v;
    }
    red[tid] = s2;
    __syncthreads();
    for (int t = 128; t > 0; t >>= 1) {
        if (tid < t) red[tid] += red[tid + t];
        __syncthreads();
    }
    float rstd = rsqrtf(red[0] * (1.0f / DM) + 1e-5f);
    __syncthreads();
    for (int d = tid; d < DM; d += 256) {
        float v = (buf[d] - mu) * rstd * g[d] + b[d];
        out[(size_t)row * DM + d] = v;
        outb[(size_t)row * DM + d] = __float2bfloat16(v);
    }
}

// ---------------- single-pass online log-softmax NLL ----------------
__global__ void __launch_bounds__(256)
loss_kernel(const float* __restrict__ logits, const float* __restrict__ ob,
            const int* __restrict__ target, float* __restrict__ out) {
    int row = blockIdx.x;
    const float* lr = logits + (size_t)row * NV;
    __shared__ float mred[256];
    __shared__ float sred[256];
    int tid = threadIdx.x;
    float m = -1e30f, s = 0.0f;
    for (int v = tid; v < NV; v += 256) {
        float x = lr[v] + ob[v];
        if (x > m) { s = s * expf(m - x) + 1.0f; m = x; }
        else        s += expf(x - m);
    }
    mred[tid] = m; sred[tid] = s;
    __syncthreads();
    for (int t = 128; t > 0; t >>= 1) {
        if (tid < t) {
            float ma = mred[tid], mb = mred[tid + t];
            float M = fmaxf(ma, mb);
            sred[tid] = sred[tid] * expf(ma - M) + sred[tid + t] * expf(mb - M);
            mred[tid] = M;
        }
        __syncthreads();
    }
    if (tid == 0) {
        int t = target[row];
        out[row] = -(lr[t] + ob[t] - mred[0] - logf(sred[0]));
    }
}

// ---------------- driver ----------------
static inline void conv(const float* src, bf16* dst, size_t n) {
    size_t n8 = n / 8;
    f2b_kernel<<<(unsigned)((n8 + 255) / 256), 256>>>(src, dst, n8);
}

extern "C" void kernel_launch(void* const* d_in, const int* in_sizes, int n_in,
                              void* d_out, int out_size) {
    const int*   data     = (const int*)d_in[0];
    const int*   target   = (const int*)d_in[1];
    const float* mems     = (const float*)d_in[2];
    const float* emb      = (const float*)d_in[3];
    const float* out_bias = (const float*)d_in[4];
    const float* rwb      = (const float*)d_in[5];
    const float* rrb      = (const float*)d_in[6];
    const float* qkv_w    = (const float*)d_in[7];
    const float* r_w      = (const float*)d_in[8];
    const float* o_w      = (const float*)d_in[9];
    const float* ln1g     = (const float*)d_in[10];
    const float* ln1b     = (const float*)d_in[11];
    const float* ff1w     = (const float*)d_in[12];
    const float* ff1b     = (const float*)d_in[13];
    const float* ff2w     = (const float*)d_in[14];
    const float* ff2b     = (const float*)d_in[15];
    const float* ln2g     = (const float*)d_in[16];
    const float* ln2b     = (const float*)d_in[17];
    float* out = (float*)d_out;

    // raise dynamic-smem limit for big-tile GEMM (idempotent)
    cudaFuncSetAttribute(wgemmB<0>, cudaFuncAttributeMaxDynamicSharedMemorySize, BG_SMEM);
    cudaFuncSetAttribute(wgemmB<1>, cudaFuncAttributeMaxDynamicSharedMemorySize, BG_SMEM);
    cudaFuncSetAttribute(wgemmB<2>, cudaFuncAttributeMaxDynamicSharedMemorySize, BG_SMEM);

    float *p_h, *p_S, *p_D, *p_ao, *p_ff, *p_logits;
    bf16 *q_qkv, *q_r, *q_o, *q_f1, *q_f2, *q_emb;
    bf16 *c_cat, *c_heads, *c_pos, *c_r, *c_qc, *c_qr, *c_P, *c_av, *c_h, *c_ffh;
    cudaGetSymbolAddress((void**)&p_h, g_h);
    cudaGetSymbolAddress((void**)&p_S, g_S);
    cudaGetSymbolAddress((void**)&p_D, g_D);
    cudaGetSymbolAddress((void**)&p_ao, g_ao);
    cudaGetSymbolAddress((void**)&p_ff, g_ff);
    cudaGetSymbolAddress((void**)&p_logits, g_logits);
    cudaGetSymbolAddress((void**)&q_qkv, wb_qkv);
    cudaGetSymbolAddress((void**)&q_r, wb_r);
    cudaGetSymbolAddress((void**)&q_o, wb_o);
    cudaGetSymbolAddress((void**)&q_f1, wb_f1);
    cudaGetSymbolAddress((void**)&q_f2, wb_f2);
    cudaGetSymbolAddress((void**)&q_emb, wb_emb);
    cudaGetSymbolAddress((void**)&c_cat, b_cat);
    cudaGetSymbolAddress((void**)&c_heads, b_heads);
    cudaGetSymbolAddress((void**)&c_pos, b_pos);
    cudaGetSymbolAddress((void**)&c_r, b_r);
    cudaGetSymbolAddress((void**)&c_qc, b_qc);
    cudaGetSymbolAddress((void**)&c_qr, b_qr);
    cudaGetSymbolAddress((void**)&c_P, b_P);
    cudaGetSymbolAddress((void**)&c_av, b_av);
    cudaGetSymbolAddress((void**)&c_h, b_h);
    cudaGetSymbolAddress((void**)&c_ffh, b_ffh);

    conv(qkv_w, q_qkv, (size_t)NL * HD3 * DM);
    conv(r_w,   q_r,   (size_t)NL * DM * DM);
    conv(o_w,   q_o,   (size_t)NL * DM * DM);
    conv(ff1w,  q_f1,  (size_t)NL * DI * DM);
    conv(ff2w,  q_f2,  (size_t)NL * DI * DM);
    conv(emb,   q_emb, (size_t)NV * DM);

    posemb_kernel<<<KL, 512>>>(c_pos);
    embed_kernel<<<QL * BSZ, 256>>>(data, emb, p_h);

    for (int l = 0; l < NL; l++) {
        concat_kernel<<<KL * BSZ, 256>>>(mems + (size_t)l * ML * BSZ * DM, p_h, c_cat);

        // heads = cat @ qkv_w^T : M=4096, N=3072, K=1024 -> bf16 (big tile)
        wgemmB<1><<<dim3(32, 12), 256, BG_SMEM>>>(c_cat, DM, q_qkv + (size_t)l * HD3 * DM, DM,
                                                  c_heads, HD3, nullptr, DM);
        // r = pos @ r_w^T : M=1024, N=1024, K=1024 -> bf16 (big tile)
        wgemmB<1><<<dim3(8, 4), 256, BG_SMEM>>>(c_pos, DM, q_r + (size_t)l * DM * DM, DM,
                                                c_r, DM, nullptr, DM);
        qcqr_kernel<<<dim3(QL, BSZ), 256>>>(c_heads, rwb, rrb, c_qc, c_qr);

        // AC[z] = qc[z] @ K[z]^T : M=512, N=1024, K=64 -> fp32 (wmma 128x128)
        wgemmb<0, 0><<<dim3(4, 8, 64), 256>>>(c_qc, DH, (size_t)4 * QL * DH, (size_t)QL * DH,
                                              c_heads + NH * DH, BSZ * HD3, DH, HD3,
                                              p_S, KL, (size_t)4 * QL * KL, (size_t)QL * KL,
                                              nullptr, KL, DH);
        // D[z] = qr[z] @ r^T (head slice) : M=512, N=1024, K=64 -> fp32
        wgemmb<0, 0><<<dim3(4, 8, 64), 256>>>(c_qr, DH, (size_t)4 * QL * DH, (size_t)QL * DH,
                                              c_r, DM, DH, 0,
                                              p_D, KL, (size_t)4 * QL * KL, (size_t)QL * KL,
                                              nullptr, KL, DH);
        softmax_kernel<<<dim3(QL, BSZ * NH), 256>>>(p_S, p_D, c_P);

        // attn_vec[z] = P[z] @ V[z] : M=512, N=64, K=1024 (NN) -> bf16
        wgemmb<1, 1><<<dim3(4, 1, 64), 256>>>(c_P, KL, (size_t)4 * QL * KL, (size_t)QL * KL,
                                              c_heads + 2 * NH * DH, BSZ * HD3, DH, HD3,
                                              c_av, BSZ * DM, DH, DM, nullptr,
                                              DH, KL);
        // attn_out = attn_vec @ o_w^T : M=2048, N=1024, K=1024 -> fp32 (big tile)
        wgemmB<0><<<dim3(16, 4), 256, BG_SMEM>>>(c_av, DM, q_o + (size_t)l * DM * DM, DM,
                                                 p_ao, DM, nullptr, DM);
        ln_kernel<<<QL * BSZ, 256>>>(p_h, p_ao, nullptr,
                                     ln1g + l * DM, ln1b + l * DM, p_h, c_h);

        // ffh = relu(h @ ff1_w^T + b) : M=2048, N=4096, K=1024 -> bf16 fused (big tile)
        wgemmB<2><<<dim3(16, 16), 256, BG_SMEM>>>(c_h, DM, q_f1 + (size_t)l * DI * DM, DM,
                                                  c_ffh, DI, ff1b + (size_t)l * DI, DM);
        // ff = ffh @ ff2_w^T : M=2048, N=1024, K=4096 -> fp32 (big tile)
        wgemmB<0><<<dim3(16, 4), 256, BG_SMEM>>>(c_ffh, DI, q_f2 + (size_t)l * DM * DI, DI,
                                                 p_ff, DM, nullptr, DI);
        ln_kernel<<<QL * BSZ, 256>>>(p_h, p_ff, ff2b + (size_t)l * DM,
                                     ln2g + l * DM, ln2b + l * DM, p_h, c_h);
    }

    // logits = h @ emb^T : M=2048, N=32000, K=1024 -> fp32 (big tile)
    wgemmB<0><<<dim3(16, 125), 256, BG_SMEM>>>(c_h, DM, q_emb, DM,
                                               p_logits, NV, nullptr, DM);
    loss_kernel<<<QL * BSZ, 256>>>(p_logits, out_bias, target, out);
}

// round 16
// speedup vs baseline: 1.8647x; 1.8647x over previous
#include <cuda_runtime.h>
#include <cuda_bf16.h>
#include <mma.h>
#include <math.h>
#include <cstdint>

using namespace nvcuda;
typedef __nv_bfloat16 bf16;

// ---------------- problem constants ----------------
#define QL 512
#define ML 512
#define KL 1024          // QL + ML
#define BSZ 4
#define NH 16
#define DH 64
#define DM 1024
#define DI 4096
#define NV 32000
#define NL 6
#define HD3 3072         // 3*NH*DH

// ---------------- fp32 scratch ----------------
__device__ float g_h[(size_t)QL * BSZ * DM];
__device__ float g_S[(size_t)BSZ * NH * QL * KL];     // AC
__device__ float g_D[(size_t)BSZ * NH * QL * KL];     // BD (unshifted)
__device__ float g_ao[(size_t)QL * BSZ * DM];
__device__ float g_ff[(size_t)QL * BSZ * DM];
__device__ float g_logits[(size_t)QL * BSZ * NV];

// ---------------- bf16 weight arena ----------------
__device__ bf16 wb_qkv[(size_t)NL * HD3 * DM];
__device__ bf16 wb_r[(size_t)NL * DM * DM];
__device__ bf16 wb_o[(size_t)NL * DM * DM];
__device__ bf16 wb_f1[(size_t)NL * DI * DM];
__device__ bf16 wb_f2[(size_t)NL * DI * DM];
__device__ bf16 wb_emb[(size_t)NV * DM];

// ---------------- bf16 activation buffers ----------------
__device__ bf16 b_cat[(size_t)KL * BSZ * DM];
__device__ bf16 b_heads[(size_t)KL * BSZ * HD3];
__device__ bf16 b_pos[(size_t)KL * DM];
__device__ bf16 b_r[(size_t)KL * DM];
__device__ bf16 b_qc[(size_t)BSZ * NH * QL * DH];
__device__ bf16 b_qr[(size_t)BSZ * NH * QL * DH];
__device__ bf16 b_P[(size_t)BSZ * NH * QL * KL];
__device__ bf16 b_av[(size_t)QL * BSZ * DM];
__device__ bf16 b_h[(size_t)QL * BSZ * DM];
__device__ bf16 b_ffh[(size_t)QL * BSZ * DI];

// ---------------- cp.async helpers ----------------
__device__ __forceinline__ void cpa16(void* dst, const void* src, bool pred) {
    unsigned d = (unsigned)__cvta_generic_to_shared(dst);
    int sz = pred ? 16 : 0;
    asm volatile("cp.async.cg.shared.global [%0], [%1], 16, %2;\n"
                 :: "r"(d), "l"(src), "r"(sz));
}
__device__ __forceinline__ void cpa_commit() {
    asm volatile("cp.async.commit_group;\n" ::: "memory");
}

// ---------------- fp32 -> bf16 bulk convert ----------------
__global__ void f2b_kernel(const float* __restrict__ in, bf16* __restrict__ out, size_t n8) {
    size_t i = (size_t)blockIdx.x * 256 + threadIdx.x;
    if (i >= n8) return;
    const float4* in4 = (const float4*)in;
    float4 a = in4[2 * i], b = in4[2 * i + 1];
    __nv_bfloat162 h0 = __floats2bfloat162_rn(a.x, a.y);
    __nv_bfloat162 h1 = __floats2bfloat162_rn(a.z, a.w);
    __nv_bfloat162 h2 = __floats2bfloat162_rn(b.x, b.y);
    __nv_bfloat162 h3 = __floats2bfloat162_rn(b.z, b.w);
    uint4 u;
    u.x = *(unsigned*)&h0; u.y = *(unsigned*)&h1;
    u.z = *(unsigned*)&h2; u.w = *(unsigned*)&h3;
    ((uint4*)out)[i] = u;
}

// ---------------- positional embedding (bf16) ----------------
__global__ void posemb_kernel(bf16* __restrict__ pos) {
    int p = blockIdx.x;
    int j = threadIdx.x;
    float posv = (float)(KL - 1 - p);
    float inv = expf(-(float)(2 * j) * (9.210340371976184f / 1024.0f));
    float a = posv * inv;
    pos[(size_t)p * DM + j]       = __float2bfloat16(sinf(a));
    pos[(size_t)p * DM + 512 + j] = __float2bfloat16(cosf(a));
}

// ---------------- embedding lookup (fp32 residual) ----------------
__global__ void embed_kernel(const int* __restrict__ data,
                             const float* __restrict__ emb,
                             float* __restrict__ h) {
    int row = blockIdx.x;
    int tok = data[row];
    const float4* src = (const float4*)(emb + (size_t)tok * DM);
    float4* dst = (float4*)(h + (size_t)row * DM);
    int d = threadIdx.x;
    float4 f = src[d];
    f.x *= 32.0f; f.y *= 32.0f; f.z *= 32.0f; f.w *= 32.0f;
    dst[d] = f;
}

// ---------------- concat [mems_l ; h] -> bf16 cat ----------------
__global__ void concat_kernel(const float* __restrict__ mems_l,
                              const float* __restrict__ h,
                              bf16* __restrict__ cat) {
    int row = blockIdx.x;
    const float4* src = (row < ML * BSZ)
        ? (const float4*)(mems_l + (size_t)row * DM)
        : (const float4*)(h + (size_t)(row - ML * BSZ) * DM);
    float4 f = src[threadIdx.x];
    __nv_bfloat162 h0 = __floats2bfloat162_rn(f.x, f.y);
    __nv_bfloat162 h1 = __floats2bfloat162_rn(f.z, f.w);
    uint2 u; u.x = *(unsigned*)&h0; u.y = *(unsigned*)&h1;
    ((uint2*)(cat + (size_t)row * DM))[threadIdx.x] = u;
}

// ---------------- WIDE-WARP bf16 wmma GEMM (NT): C[m,n] = sum_k A[m,k]*B[n,k] ----------------
// Block 128x128x32, 128 threads, 4 warps (2x2), warp tile 64x64 (4x4 m16n16k16).
// 2 CTAs/SM (40KB static smem). M,N multiples of 128; K mult 32.
// OUT: 0 fp32, 1 bf16, 2 bf16 +bias,relu.
template <int OUT>
__global__ void __launch_bounds__(128, 2)
wgemmW(const bf16* __restrict__ A, int lda,
       const bf16* __restrict__ B, int ldb,
       void* __restrict__ Cv, int ldc,
       const float* __restrict__ bias, int K) {
    __shared__ __align__(16) bf16 As[2][128 * 40];
    __shared__ __align__(16) bf16 Bs[2][128 * 40];
    int tid = threadIdx.x;
    int warp = tid >> 5, wr = warp >> 1, wc = warp & 1;
    int lane = tid & 31;
    int m0 = blockIdx.x * 128, n0 = blockIdx.y * 128;

    wmma::fragment<wmma::accumulator, 16, 16, 16, float> acc[4][4];
#pragma unroll
    for (int i = 0; i < 4; i++)
#pragma unroll
        for (int j = 0; j < 4; j++) wmma::fill_fragment(acc[i][j], 0.0f);

    // loader: 512 16B-chunks per matrix, 128 threads -> 4 chunks each
    auto load_stage = [&](int st, int k0) {
#pragma unroll
        for (int q = 0; q < 4; q++) {
            int c = tid + 128 * q;             // 0..511
            int row = c >> 2, col8 = (c & 3) * 8;
            cpa16(&As[st][row * 40 + col8], A + (size_t)(m0 + row) * lda + k0 + col8, true);
            cpa16(&Bs[st][row * 40 + col8], B + (size_t)(n0 + row) * ldb + k0 + col8, true);
        }
        cpa_commit();
    };

    int nk = K >> 5;
    load_stage(0, 0);
    for (int i = 0; i < nk; i++) {
        int st = i & 1;
        if (i + 1 < nk) {
            load_stage(st ^ 1, (i + 1) << 5);
            asm volatile("cp.async.wait_group 1;\n" ::: "memory");
        } else {
            asm volatile("cp.async.wait_group 0;\n" ::: "memory");
        }
        __syncthreads();

#pragma unroll
        for (int ks = 0; ks < 2; ks++) {
            wmma::fragment<wmma::matrix_a, 16, 16, 16, bf16, wmma::row_major> af[4];
#pragma unroll
            for (int mi = 0; mi < 4; mi++)
                wmma::load_matrix_sync(af[mi], &As[st][(wr * 64 + mi * 16) * 40 + ks * 16], 40);
#pragma unroll
            for (int ni = 0; ni < 4; ni++) {
                wmma::fragment<wmma::matrix_b, 16, 16, 16, bf16, wmma::col_major> bfr;
                wmma::load_matrix_sync(bfr, &Bs[st][(wc * 64 + ni * 16) * 40 + ks * 16], 40);
#pragma unroll
                for (int mi = 0; mi < 4; mi++)
                    wmma::mma_sync(acc[mi][ni], af[mi], bfr, acc[mi][ni]);
            }
        }
        __syncthreads();
    }

    if (OUT == 0) {
        float* Cb = (float*)Cv;
#pragma unroll
        for (int mi = 0; mi < 4; mi++)
#pragma unroll
            for (int ni = 0; ni < 4; ni++)
                wmma::store_matrix_sync(
                    Cb + (size_t)(m0 + wr * 64 + mi * 16) * ldc + n0 + wc * 64 + ni * 16,
                    acc[mi][ni], ldc, wmma::mem_row_major);
    } else {
        bf16* Cb = (bf16*)Cv;
        float* wbuf = ((float*)As) + warp * 320;   // 16x20 fp32 staging, ldm=20 (80B, 16B-mult)
        int r = lane >> 1, ch = (lane & 1) * 8;
#pragma unroll
        for (int mi = 0; mi < 4; mi++)
#pragma unroll
            for (int ni = 0; ni < 4; ni++) {
                wmma::store_matrix_sync(wbuf, acc[mi][ni], 20, wmma::mem_row_major);
                __syncwarp();
                int gn = n0 + wc * 64 + ni * 16 + ch;
                int gm = m0 + wr * 64 + mi * 16 + r;
                float v[8];
#pragma unroll
                for (int t = 0; t < 8; t++) v[t] = wbuf[r * 20 + ch + t];
                if (OUT == 2) {
#pragma unroll
                    for (int t = 0; t < 8; t++) v[t] = fmaxf(v[t] + bias[gn + t], 0.0f);
                }
                __nv_bfloat162 h0 = __floats2bfloat162_rn(v[0], v[1]);
                __nv_bfloat162 h1 = __floats2bfloat162_rn(v[2], v[3]);
                __nv_bfloat162 h2 = __floats2bfloat162_rn(v[4], v[5]);
                __nv_bfloat162 h3 = __floats2bfloat162_rn(v[6], v[7]);
                uint4 u;
                u.x = *(unsigned*)&h0; u.y = *(unsigned*)&h1;
                u.z = *(unsigned*)&h2; u.w = *(unsigned*)&h3;
                *(uint4*)(Cb + (size_t)gm * ldc + gn) = u;
                __syncwarp();
            }
    }
}

// ---------------- bf16 wmma GEMM, 128x128, 256 thr (attention shapes, batched) ----------------
template <int BROW, int OUT>
__global__ void __launch_bounds__(256, 2)
wgemmb(const bf16* __restrict__ A, int lda, size_t sA1, size_t sA2,
       const bf16* __restrict__ B, int ldb, size_t sB1, size_t sB2,
       void* __restrict__ Cv, int ldc, size_t sC1, size_t sC2,
       const float* __restrict__ bias, int N, int K) {
    int zn = blockIdx.z >> 2, zb = blockIdx.z & 3;
    const bf16* Ab = A + (size_t)zn * sA1 + (size_t)zb * sA2;
    const bf16* Bb = B + (size_t)zn * sB1 + (size_t)zb * sB2;
    int m0 = blockIdx.x * 128, n0 = blockIdx.y * 128;
    int tid = threadIdx.x;
    int warp = tid >> 5, wr = warp >> 2, wc = warp & 3;
    int lane = tid & 31;

    __shared__ __align__(16) bf16 As[2][128 * 40];
    __shared__ __align__(16) bf16 Bs[2][128 * 40];

    wmma::fragment<wmma::accumulator, 16, 16, 16, float> acc[4][2];
#pragma unroll
    for (int i = 0; i < 4; i++)
#pragma unroll
        for (int j = 0; j < 2; j++) wmma::fill_fragment(acc[i][j], 0.0f);

    int arow0 = tid >> 2, ac0 = (tid & 3) * 8, arow1 = arow0 + 64;
    int kr0 = 0, kr1 = 0, nc0 = 0;
    bool g0 = true, g1 = true, gn = true;
    if (BROW == 0) {
        g0 = (n0 + arow0) < N;
        g1 = (n0 + arow1) < N;
    } else {
        kr0 = tid >> 4; kr1 = kr0 + 16;
        nc0 = (tid & 15) * 8;
        gn = (n0 + nc0) < N;
    }

    auto load_stage = [&](int st, int k0) {
        cpa16(&As[st][arow0 * 40 + ac0], Ab + (size_t)(m0 + arow0) * lda + k0 + ac0, true);
        cpa16(&As[st][arow1 * 40 + ac0], Ab + (size_t)(m0 + arow1) * lda + k0 + ac0, true);
        if (BROW == 0) {
            cpa16(&Bs[st][arow0 * 40 + ac0], Bb + (size_t)(n0 + arow0) * ldb + k0 + ac0, g0);
            cpa16(&Bs[st][arow1 * 40 + ac0], Bb + (size_t)(n0 + arow1) * ldb + k0 + ac0, g1);
        } else {
            cpa16(&Bs[st][kr0 * 136 + nc0], Bb + (size_t)(k0 + kr0) * ldb + n0 + nc0, gn);
            cpa16(&Bs[st][kr1 * 136 + nc0], Bb + (size_t)(k0 + kr1) * ldb + n0 + nc0, gn);
        }
        cpa_commit();
    };

    int nk = K >> 5;
    load_stage(0, 0);
    for (int i = 0; i < nk; i++) {
        int st = i & 1;
        if (i + 1 < nk) {
            load_stage(st ^ 1, (i + 1) << 5);
            asm volatile("cp.async.wait_group 1;\n" ::: "memory");
        } else {
            asm volatile("cp.async.wait_group 0;\n" ::: "memory");
        }
        __syncthreads();

#pragma unroll
        for (int ks = 0; ks < 2; ks++) {
            wmma::fragment<wmma::matrix_a, 16, 16, 16, bf16, wmma::row_major> af[4];
#pragma unroll
            for (int mi = 0; mi < 4; mi++)
                wmma::load_matrix_sync(af[mi], &As[st][(wr * 64 + mi * 16) * 40 + ks * 16], 40);
            if (BROW == 0) {
                wmma::fragment<wmma::matrix_b, 16, 16, 16, bf16, wmma::col_major> bfr[2];
#pragma unroll
                for (int ni = 0; ni < 2; ni++)
                    wmma::load_matrix_sync(bfr[ni], &Bs[st][(wc * 32 + ni * 16) * 40 + ks * 16], 40);
#pragma unroll
                for (int mi = 0; mi < 4; mi++)
#pragma unroll
                    for (int ni = 0; ni < 2; ni++)
                        wmma::mma_sync(acc[mi][ni], af[mi], bfr[ni], acc[mi][ni]);
            } else {
                wmma::fragment<wmma::matrix_b, 16, 16, 16, bf16, wmma::row_major> bfr[2];
#pragma unroll
                for (int ni = 0; ni < 2; ni++)
                    wmma::load_matrix_sync(bfr[ni], &Bs[st][ks * 16 * 136 + wc * 32 + ni * 16], 136);
#pragma unroll
                for (int mi = 0; mi < 4; mi++)
#pragma unroll
                    for (int ni = 0; ni < 2; ni++)
                        wmma::mma_sync(acc[mi][ni], af[mi], bfr[ni], acc[mi][ni]);
            }
        }
        __syncthreads();
    }

    if (OUT == 0) {
        float* Cb = (float*)Cv + (size_t)zn * sC1 + (size_t)zb * sC2;
#pragma unroll
        for (int mi = 0; mi < 4; mi++)
#pragma unroll
            for (int ni = 0; ni < 2; ni++) {
                int cn = n0 + wc * 32 + ni * 16;
                if (cn < N)
                    wmma::store_matrix_sync(Cb + (size_t)(m0 + wr * 64 + mi * 16) * ldc + cn,
                                            acc[mi][ni], ldc, wmma::mem_row_major);
            }
    } else {
        bf16* Cb = (bf16*)Cv + (size_t)zn * sC1 + (size_t)zb * sC2;
        float* wbuf = ((float*)As) + warp * 320;
        int r = lane >> 1, ch = (lane & 1) * 8;
#pragma unroll
        for (int mi = 0; mi < 4; mi++)
#pragma unroll
            for (int ni = 0; ni < 2; ni++) {
                wmma::store_matrix_sync(wbuf, acc[mi][ni], 20, wmma::mem_row_major);
                __syncwarp();
                int gn = n0 + wc * 32 + ni * 16 + ch;
                if (gn < N) {
                    int gm = m0 + wr * 64 + mi * 16 + r;
                    float v[8];
#pragma unroll
                    for (int t = 0; t < 8; t++) v[t] = wbuf[r * 20 + ch + t];
                    if (OUT == 2) {
#pragma unroll
                        for (int t = 0; t < 8; t++) v[t] = fmaxf(v[t] + bias[gn + t], 0.0f);
                    }
                    __nv_bfloat162 h0 = __floats2bfloat162_rn(v[0], v[1]);
                    __nv_bfloat162 h1 = __floats2bfloat162_rn(v[2], v[3]);
                    __nv_bfloat162 h2 = __floats2bfloat162_rn(v[4], v[5]);
                    __nv_bfloat162 h3 = __floats2bfloat162_rn(v[6], v[7]);
                    uint4 u;
                    u.x = *(unsigned*)&h0; u.y = *(unsigned*)&h1;
                    u.z = *(unsigned*)&h2; u.w = *(unsigned*)&h3;
                    *(uint4*)(Cb + (size_t)gm * ldc + gn) = u;
                }
                __syncwarp();
            }
    }
}

// ---------------- qc = q + r_w_bias, qr = q + r_r_bias (bf16 in/out) ----------------
__global__ void qcqr_kernel(const bf16* __restrict__ heads,
                            const float* __restrict__ rwb, const float* __restrict__ rrb,
                            bf16* __restrict__ qc, bf16* __restrict__ qr) {
    int i = blockIdx.x, b = blockIdx.y;
    int tid = threadIdx.x;
#pragma unroll
    for (int k = 0; k < 4; k++) {
        int dg = tid + k * 256;
        int n = dg >> 6, d = dg & 63;
        float q = __bfloat162float(heads[((size_t)(ML + i) * BSZ + b) * HD3 + n * DH + d]);
        size_t o = ((size_t)(n * 4 + b) * QL + i) * DH + d;
        qc[o] = __float2bfloat16(q + rwb[dg]);
        qr[o] = __float2bfloat16(q + rrb[dg]);
    }
}

// ---------------- fused rel-shift + mask + softmax -> bf16 P ----------------
__global__ void __launch_bounds__(256)
softmax_kernel(const float* __restrict__ S, const float* __restrict__ D,
               bf16* __restrict__ P) {
    int i = blockIdx.x;
    int z = blockIdx.y;
    const float* row = S + ((size_t)z * QL + i) * KL;
    const float* drow = D + ((size_t)z * QL + i) * KL + (QL - 1 - i);
    bf16* prow = P + ((size_t)z * QL + i) * KL;
    int jmax = i + ML;
    __shared__ float sc[KL];
    __shared__ float red[256];
    int tid = threadIdx.x;

    float mx = -1e30f;
    for (int j = tid; j <= jmax; j += 256) {
        float s = (row[j] + drow[j]) * 0.125f;
        sc[j] = s;
        mx = fmaxf(mx, s);
    }
    red[tid] = mx;
    __syncthreads();
    for (int t = 128; t > 0; t >>= 1) {
        if (tid < t) red[tid] = fmaxf(red[tid], red[tid + t]);
        __syncthreads();
    }
    float m = red[0];
    __syncthreads();

    float sum = 0.0f;
    for (int j = tid; j <= jmax; j += 256) {
        float e = expf(sc[j] - m);
        sc[j] = e;
        sum += e;
    }
    red[tid] = sum;
    __syncthreads();
    for (int t = 128; t > 0; t >>= 1) {
        if (tid < t) red[tid] += red[tid + t];
        __syncthreads();
    }
    float inv = 1.0f / red[0];
    __syncthreads();

    for (int j = tid; j <= jmax; j += 256) prow[j] = __float2bfloat16(sc[j] * inv);
    bf16 zero = __float2bfloat16(0.0f);
    for (int j = jmax + 1 + tid; j < KL; j += 256) prow[j] = zero;
}

// ---------------- fused residual (+bias) + layernorm; fp32 + bf16 outputs ----------------
__global__ void __launch_bounds__(256)
ln_kernel(const float* __restrict__ x, const float* __restrict__ y,
          const float* __restrict__ extra,
          const float* __restrict__ g, const float* __restrict__ b,
          float* __restrict__ out, bf16* __restrict__ outb) {
    int row = blockIdx.x;
    __shared__ float buf[DM];
    __shared__ float red[256];
    int tid = threadIdx.x;
    float s = 0.0f;
    for (int d = tid; d < DM; d += 256) {
        float v = x[(size_t)row * DM + d] + y[(size_t)row * DM + d];
        if (extra) v += extra[d];
        buf[d] = v;
        s += v;
    }
    red[tid] = s;
    __syncthreads();
    for (int t = 128; t > 0; t >>= 1) {
        if (tid < t) red[tid] += red[tid + t];
        __syncthreads();
    }
    float mu = red[0] * (1.0f / DM);
    __syncthreads();
    float s2 = 0.0f;
    for (int d = tid; d < DM; d += 256) {
        float v = buf[d] - mu;
        s2 += v * v;
    }
    red[tid] = s2;
    __syncthreads();
    for (int t = 128; t > 0; t >>= 1) {
        if (tid < t) red[tid] += red[tid + t];
        __syncthreads();
    }
    float rstd = rsqrtf(red[0] * (1.0f / DM) + 1e-5f);
    __syncthreads();
    for (int d = tid; d < DM; d += 256) {
        float v = (buf[d] - mu) * rstd * g[d] + b[d];
        out[(size_t)row * DM + d] = v;
        outb[(size_t)row * DM + d] = __float2bfloat16(v);
    }
}

// ---------------- single-pass online log-softmax NLL ----------------
__global__ void __launch_bounds__(256)
loss_kernel(const float* __restrict__ logits, const float* __restrict__ ob,
            const int* __restrict__ target, float* __restrict__ out) {
    int row = blockIdx.x;
    const float* lr = logits + (size_t)row * NV;
    __shared__ float mred[256];
    __shared__ float sred[256];
    int tid = threadIdx.x;
    float m = -1e30f, s = 0.0f;
    for (int v = tid; v < NV; v += 256) {
        float x = lr[v] + ob[v];
        if (x > m) { s = s * expf(m - x) + 1.0f; m = x; }
        else        s += expf(x - m);
    }
    mred[tid] = m; sred[tid] = s;
    __syncthreads();
    for (int t = 128; t > 0; t >>= 1) {
        if (tid < t) {
            float ma = mred[tid], mb = mred[tid + t];
            float M = fmaxf(ma, mb);
            sred[tid] = sred[tid] * expf(ma - M) + sred[tid + t] * expf(mb - M);
            mred[tid] = M;
        }
        __syncthreads();
    }
    if (tid == 0) {
        int t = target[row];
        out[row] = -(lr[t] + ob[t] - mred[0] - logf(sred[0]));
    }
}

// ---------------- driver ----------------
static inline void conv(const float* src, bf16* dst, size_t n) {
    size_t n8 = n / 8;
    f2b_kernel<<<(unsigned)((n8 + 255) / 256), 256>>>(src, dst, n8);
}

extern "C" void kernel_launch(void* const* d_in, const int* in_sizes, int n_in,
                              void* d_out, int out_size) {
    const int*   data     = (const int*)d_in[0];
    const int*   target   = (const int*)d_in[1];
    const float* mems     = (const float*)d_in[2];
    const float* emb      = (const float*)d_in[3];
    const float* out_bias = (const float*)d_in[4];
    const float* rwb      = (const float*)d_in[5];
    const float* rrb      = (const float*)d_in[6];
    const float* qkv_w    = (const float*)d_in[7];
    const float* r_w      = (const float*)d_in[8];
    const float* o_w      = (const float*)d_in[9];
    const float* ln1g     = (const float*)d_in[10];
    const float* ln1b     = (const float*)d_in[11];
    const float* ff1w     = (const float*)d_in[12];
    const float* ff1b     = (const float*)d_in[13];
    const float* ff2w     = (const float*)d_in[14];
    const float* ff2b     = (const float*)d_in[15];
    const float* ln2g     = (const float*)d_in[16];
    const float* ln2b     = (const float*)d_in[17];
    float* out = (float*)d_out;

    float *p_h, *p_S, *p_D, *p_ao, *p_ff, *p_logits;
    bf16 *q_qkv, *q_r, *q_o, *q_f1, *q_f2, *q_emb;
    bf16 *c_cat, *c_heads, *c_pos, *c_r, *c_qc, *c_qr, *c_P, *c_av, *c_h, *c_ffh;
    cudaGetSymbolAddress((void**)&p_h, g_h);
    cudaGetSymbolAddress((void**)&p_S, g_S);
    cudaGetSymbolAddress((void**)&p_D, g_D);
    cudaGetSymbolAddress((void**)&p_ao, g_ao);
    cudaGetSymbolAddress((void**)&p_ff, g_ff);
    cudaGetSymbolAddress((void**)&p_logits, g_logits);
    cudaGetSymbolAddress((void**)&q_qkv, wb_qkv);
    cudaGetSymbolAddress((void**)&q_r, wb_r);
    cudaGetSymbolAddress((void**)&q_o, wb_o);
    cudaGetSymbolAddress((void**)&q_f1, wb_f1);
    cudaGetSymbolAddress((void**)&q_f2, wb_f2);
    cudaGetSymbolAddress((void**)&q_emb, wb_emb);
    cudaGetSymbolAddress((void**)&c_cat, b_cat);
    cudaGetSymbolAddress((void**)&c_heads, b_heads);
    cudaGetSymbolAddress((void**)&c_pos, b_pos);
    cudaGetSymbolAddress((void**)&c_r, b_r);
    cudaGetSymbolAddress((void**)&c_qc, b_qc);
    cudaGetSymbolAddress((void**)&c_qr, b_qr);
    cudaGetSymbolAddress((void**)&c_P, b_P);
    cudaGetSymbolAddress((void**)&c_av, b_av);
    cudaGetSymbolAddress((void**)&c_h, b_h);
    cudaGetSymbolAddress((void**)&c_ffh, b_ffh);

    conv(qkv_w, q_qkv, (size_t)NL * HD3 * DM);
    conv(r_w,   q_r,   (size_t)NL * DM * DM);
    conv(o_w,   q_o,   (size_t)NL * DM * DM);
    conv(ff1w,  q_f1,  (size_t)NL * DI * DM);
    conv(ff2w,  q_f2,  (size_t)NL * DI * DM);
    conv(emb,   q_emb, (size_t)NV * DM);

    posemb_kernel<<<KL, 512>>>(c_pos);
    embed_kernel<<<QL * BSZ, 256>>>(data, emb, p_h);

    for (int l = 0; l < NL; l++) {
        concat_kernel<<<KL * BSZ, 256>>>(mems + (size_t)l * ML * BSZ * DM, p_h, c_cat);

        // heads = cat @ qkv_w^T : M=4096, N=3072, K=1024 -> bf16 (wide-warp)
        wgemmW<1><<<dim3(32, 24), 128>>>(c_cat, DM, q_qkv + (size_t)l * HD3 * DM, DM,
                                         c_heads, HD3, nullptr, DM);
        // r = pos @ r_w^T : M=1024, N=1024, K=1024 -> bf16 (wide-warp)
        wgemmW<1><<<dim3(8, 8), 128>>>(c_pos, DM, q_r + (size_t)l * DM * DM, DM,
                                       c_r, DM, nullptr, DM);
        qcqr_kernel<<<dim3(QL, BSZ), 256>>>(c_heads, rwb, rrb, c_qc, c_qr);

        // AC[z] = qc[z] @ K[z]^T : M=512, N=1024, K=64 -> fp32 (batched wmma)
        wgemmb<0, 0><<<dim3(4, 8, 64), 256>>>(c_qc, DH, (size_t)4 * QL * DH, (size_t)QL * DH,
                                              c_heads + NH * DH, BSZ * HD3, DH, HD3,
                                              p_S, KL, (size_t)4 * QL * KL, (size_t)QL * KL,
                                              nullptr, KL, DH);
        // D[z] = qr[z] @ r^T (head slice) : M=512, N=1024, K=64 -> fp32
        wgemmb<0, 0><<<dim3(4, 8, 64), 256>>>(c_qr, DH, (size_t)4 * QL * DH, (size_t)QL * DH,
                                              c_r, DM, DH, 0,
                                              p_D, KL, (size_t)4 * QL * KL, (size_t)QL * KL,
                                              nullptr, KL, DH);
        softmax_kernel<<<dim3(QL, BSZ * NH), 256>>>(p_S, p_D, c_P);

        // attn_vec[z] = P[z] @ V[z] : M=512, N=64, K=1024 (NN) -> bf16
        wgemmb<1, 1><<<dim3(4, 1, 64), 256>>>(c_P, KL, (size_t)4 * QL * KL, (size_t)QL * KL,
                                              c_heads + 2 * NH * DH, BSZ * HD3, DH, HD3,
                                              c_av, BSZ * DM, DH, DM, nullptr,
                                              DH, KL);
        // attn_out = attn_vec @ o_w^T : M=2048, N=1024, K=1024 -> fp32 (wide-warp)
        wgemmW<0><<<dim3(16, 8), 128>>>(c_av, DM, q_o + (size_t)l * DM * DM, DM,
                                        p_ao, DM, nullptr, DM);
        ln_kernel<<<QL * BSZ, 256>>>(p_h, p_ao, nullptr,
                                     ln1g + l * DM, ln1b + l * DM, p_h, c_h);

        // ffh = relu(h @ ff1_w^T + b) : M=2048, N=4096, K=1024 -> bf16 fused (wide-warp)
        wgemmW<2><<<dim3(16, 32), 128>>>(c_h, DM, q_f1 + (size_t)l * DI * DM, DM,
                                         c_ffh, DI, ff1b + (size_t)l * DI, DM);
        // ff = ffh @ ff2_w^T : M=2048, N=1024, K=4096 -> fp32 (wide-warp)
        wgemmW<0><<<dim3(16, 8), 128>>>(c_ffh, DI, q_f2 + (size_t)l * DM * DI, DI,
                                        p_ff, DM, nullptr, DI);
        ln_kernel<<<QL * BSZ, 256>>>(p_h, p_ff, ff2b + (size_t)l * DM,
                                     ln2g + l * DM, ln2b + l * DM, p_h, c_h);
    }

    // logits = h @ emb^T : M=2048, N=32000, K=1024 -> fp32 (wide-warp)
    wgemmW<0><<<dim3(16, 250), 128>>>(c_h, DM, q_emb, DM,
                                      p_logits, NV, nullptr, DM);
    loss_kernel<<<QL * BSZ, 256>>>(p_logits, out_bias, target, out);
}